// round 13
// baseline (speedup 1.0000x reference)
#include <cuda_runtime.h>
#include <cuda_fp16.h>
#include <math.h>
#include <stdint.h>

// ---------------- scratch (no allocation allowed) ----------------
__device__ __half g_hs[6400000];   // 50000 x 128 halves (256B-aligned rows; cols 100..103 = 0)
__device__ float  g_acc[5000000];  // 50000 x 100 fp32 (layer-1 input)
__device__ float  g_dinv[50048];
__device__ int    g_cnt[50048];    // statically zero; re-zeroed by scan23 each call
__device__ int    g_rowptr[50049];
__device__ int    g_off[50049];
__device__ int    g_adj[800064];
__device__ int    g_bsum[256];
__device__ float  g_partials[512];
__device__ float  g_norm2;

// ---------------- ||x||^2 partial sums (s2, overlaps hist) ----------------
__global__ void sumsq_kernel(const float* __restrict__ x, long n) {
    int gs = gridDim.x * blockDim.x;
    float s = 0.f;
    for (long i = (long)blockIdx.x * blockDim.x + threadIdx.x; i < n; i += gs) {
        float v = x[i];
        s += v * v;
    }
    __shared__ float sm[256];
    sm[threadIdx.x] = s;
    __syncthreads();
    for (int o = 128; o > 0; o >>= 1) {
        if (threadIdx.x < o) sm[threadIdx.x] += sm[threadIdx.x + o];
        __syncthreads();
    }
    if (threadIdx.x == 0) g_partials[blockIdx.x] = sm[0];
}

__global__ void hist_kernel(const int* __restrict__ dst, int E) {
    int i = blockIdx.x * blockDim.x + threadIdx.x;
    if (i < E) atomicAdd(&g_cnt[dst[i]], 1);
}

// ---------------- scan1: block-local scan + dinv + norm2 finalize ----------------
__global__ void scan1_kernel(int N) {
    __shared__ int sm[256];
    int node = blockIdx.x * 256 + threadIdx.x;
    int c = (node < N) ? g_cnt[node] : 0;
    if (node < N) g_dinv[node] = rsqrtf((float)(c + 1));  // +1 self-loop
    if (blockIdx.x == 0) {
        __shared__ float fm[256];
        fm[threadIdx.x] = g_partials[threadIdx.x] + g_partials[threadIdx.x + 256];
        __syncthreads();
        for (int o = 128; o > 0; o >>= 1) {
            if (threadIdx.x < o) fm[threadIdx.x] += fm[threadIdx.x + o];
            __syncthreads();
        }
        if (threadIdx.x == 0) g_norm2 = fm[0];
    }
    sm[threadIdx.x] = c;
    __syncthreads();
    for (int o = 1; o < 256; o <<= 1) {
        int v = (threadIdx.x >= o) ? sm[threadIdx.x - o] : 0;
        __syncthreads();
        sm[threadIdx.x] += v;
        __syncthreads();
    }
    if (node <= N) g_rowptr[node] = sm[threadIdx.x] - c;
    if (threadIdx.x == 255) g_bsum[blockIdx.x] = sm[255];
}

// ---------------- scan23: per-block re-scan of bsums + finalize rowptr/off/cnt ----------------
__global__ void scan23_kernel(int nb, int N, int E) {
    __shared__ int sm[256];
    int c = (threadIdx.x < nb) ? g_bsum[threadIdx.x] : 0;
    sm[threadIdx.x] = c;
    __syncthreads();
    for (int o = 1; o < 256; o <<= 1) {
        int v = (threadIdx.x >= o) ? sm[threadIdx.x - o] : 0;
        __syncthreads();
        sm[threadIdx.x] += v;
        __syncthreads();
    }
    __syncthreads();
    int boff = (blockIdx.x > 0) ? sm[blockIdx.x - 1] : 0;  // exclusive block offset
    int node = blockIdx.x * 256 + threadIdx.x;
    if (node < N) {
        int r = g_rowptr[node] + boff;
        g_rowptr[node] = r;
        g_off[node] = r;
        g_cnt[node] = 0;  // reset for next graph replay
    } else if (node == N) {
        g_rowptr[N] = E;
    }
}

__global__ void fill_kernel(const int* __restrict__ src, const int* __restrict__ dst, int E) {
    int i = blockIdx.x * blockDim.x + threadIdx.x;
    if (i < E) {
        int pos = atomicAdd(&g_off[dst[i]], 1);
        g_adj[pos] = src[i];
    }
}

// ---------------- fp16 tensor-core GEMM: hs = fp16(dinv[row] * (X @ W)) ----------------
// Writes 104 cols; cols 100..103 are exact zeros (W pads zeroed).
#define SX_STRIDE 120
__global__ void __launch_bounds__(256, 3)
gemm_mma_kernel(const float* __restrict__ X, const float* __restrict__ W,
                __half* __restrict__ hs, int N) {
    extern __shared__ __half smem_h[];
    __half* sX = smem_h;                    // 128 x 120
    __half* sWt = smem_h + 128 * SX_STRIDE; // 104 x 120 (n-major, k contiguous)
    int tid = threadIdx.x;
    int row0 = blockIdx.x * 128;
    const uint2 z2 = make_uint2(0u, 0u);

    for (int i = tid; i < 104 * SX_STRIDE / 4; i += 256)
        ((uint2*)sWt)[i] = z2;

    {
        int r = tid >> 1, h = tid & 1;
        int gr = row0 + r;
        __half* drow = sX + r * SX_STRIDE;
        if (gr < N) {
            const float4* srcp = (const float4*)(X + (size_t)gr * 100);
#pragma unroll
            for (int t = 0; t < 13; t++) {
                int c4 = h * 13 + t;
                if (c4 < 25) {
                    float4 v = __ldg(srcp + c4);
                    __half2 lo = __floats2half2_rn(v.x, v.y);
                    __half2 hi = __floats2half2_rn(v.z, v.w);
                    uint2 u;
                    u.x = *(uint32_t*)&lo; u.y = *(uint32_t*)&hi;
                    *(uint2*)(drow + c4 * 4) = u;
                }
            }
        } else {
#pragma unroll
            for (int t = 0; t < 13; t++) {
                int c4 = h * 13 + t;
                if (c4 < 25) *(uint2*)(drow + c4 * 4) = z2;
            }
        }
        if (h) {
            *(uint2*)(drow + 100) = z2;
            *(uint2*)(drow + 104) = z2;
            *(uint2*)(drow + 108) = z2;
        }
    }
    __syncthreads();

    for (int i = tid; i < 10000; i += 256) {
        int k = i / 100, n = i - k * 100;
        sWt[n * SX_STRIDE + k] = __float2half_rn(__ldg(W + i));
    }
    __syncthreads();

    int warp = tid >> 5, lane = tid & 31;
    int grp = lane >> 2, tig = lane & 3;
    const __half* xw0 = sX + (warp * 16 + grp) * SX_STRIDE;
    const __half* xw1 = xw0 + 8 * SX_STRIDE;

    float acc[13][4];
#pragma unroll
    for (int nt = 0; nt < 13; nt++)
#pragma unroll
        for (int i = 0; i < 4; i++) acc[nt][i] = 0.f;

#pragma unroll
    for (int kc = 0; kc < 7; kc++) {
        int k0 = kc * 16;
        uint32_t a0 = *(const uint32_t*)(xw0 + k0 + 2 * tig);
        uint32_t a1 = *(const uint32_t*)(xw1 + k0 + 2 * tig);
        uint32_t a2 = *(const uint32_t*)(xw0 + k0 + 2 * tig + 8);
        uint32_t a3 = *(const uint32_t*)(xw1 + k0 + 2 * tig + 8);
        const __half* wb = sWt + grp * SX_STRIDE + k0 + 2 * tig;
#pragma unroll
        for (int nt = 0; nt < 13; nt++) {
            uint32_t b0 = *(const uint32_t*)(wb + nt * 8 * SX_STRIDE);
            uint32_t b1 = *(const uint32_t*)(wb + nt * 8 * SX_STRIDE + 8);
            asm volatile(
                "mma.sync.aligned.m16n8k16.row.col.f32.f16.f16.f32 "
                "{%0,%1,%2,%3}, {%4,%5,%6,%7}, {%8,%9}, {%0,%1,%2,%3};"
                : "+f"(acc[nt][0]), "+f"(acc[nt][1]), "+f"(acc[nt][2]), "+f"(acc[nt][3])
                : "r"(a0), "r"(a1), "r"(a2), "r"(a3), "r"(b0), "r"(b1));
        }
    }

    int gr0 = row0 + warp * 16 + grp;
    int gr1 = gr0 + 8;
    float s0 = (gr0 < N) ? g_dinv[gr0] : 0.f;
    float s1 = (gr1 < N) ? g_dinv[gr1] : 0.f;
#pragma unroll
    for (int nt = 0; nt < 13; nt++) {
        int col = nt * 8 + 2 * tig;
        if (gr0 < N) {
            __half2 h = __floats2half2_rn(acc[nt][0] * s0, acc[nt][1] * s0);
            *(__half2*)(hs + (size_t)gr0 * 128 + col) = h;
        }
        if (gr1 < N) {
            __half2 h = __floats2half2_rn(acc[nt][2] * s1, acc[nt][3] * s1);
            *(__half2*)(hs + (size_t)gr1 * 128 + col) = h;
        }
    }
}

// ---- helper: accumulate a float4-worth (8 halves) into 8 fp32 ----
__device__ __forceinline__ void acc8(float* s, float4 raw) {
    __half2 h0 = *(__half2*)&raw.x;
    __half2 h1 = *(__half2*)&raw.y;
    __half2 h2 = *(__half2*)&raw.z;
    __half2 h3 = *(__half2*)&raw.w;
    float2 f0 = __half22float2(h0), f1 = __half22float2(h1);
    float2 f2 = __half22float2(h2), f3 = __half22float2(h3);
    s[0] += f0.x; s[1] += f0.y; s[2] += f1.x; s[3] += f1.y;
    s[4] += f2.x; s[5] += f2.y; s[6] += f3.x; s[7] += f3.y;
}

// ---------------- agg after layer0: acc = (dinv_i*rsqrt(norm2))*sum + cb0 (fp32) ----------------
// 13 active lanes x float4 (8 halves each; cols 100..103 are zero pads)
__global__ void __launch_bounds__(256)
agg_kernel(const __half* __restrict__ hs, float* __restrict__ acc,
           const int* __restrict__ rowptr, const int* __restrict__ adj,
           const float* __restrict__ cb, int N) {
    int node = (blockIdx.x * 256 + threadIdx.x) >> 5;
    int lane = threadIdx.x & 31;
    if (node >= N) return;
    bool act = lane < 13;

    float s[8];
#pragma unroll
    for (int i = 0; i < 8; i++) s[i] = 0.f;
    if (act) acc8(s, __ldg((const float4*)(hs + (size_t)node * 128) + lane));

    int beg = rowptr[node];
    int end = rowptr[node + 1];
    for (int base = beg; base < end; base += 32) {
        int idx = base + lane;
        int my = (idx < end) ? __ldg(adj + idx) : 0;
        int cnt = min(32, end - base);
#pragma unroll 8
        for (int j = 0; j < cnt; j++) {
            int sj = __shfl_sync(0xffffffffu, my, j);
            if (act) acc8(s, __ldg((const float4*)(hs + (size_t)sj * 128) + lane));
        }
    }
    if (act) {
        float os = g_dinv[node] * rsqrtf(g_norm2);
        float* arow = acc + (size_t)node * 100;
        float4 blo = __ldg((const float4*)cb + 2 * lane);
        float4 lo = make_float4(s[0] * os + blo.x, s[1] * os + blo.y,
                                s[2] * os + blo.z, s[3] * os + blo.w);
        *((float4*)(arow + 8 * lane)) = lo;
        if (lane < 12) {
            float4 bhi = __ldg((const float4*)cb + 2 * lane + 1);
            float4 hi = make_float4(s[4] * os + bhi.x, s[5] * os + bhi.y,
                                    s[6] * os + bhi.z, s[7] * os + bhi.w);
            *((float4*)(arow + 8 * lane + 4)) = hi;
        }
    }
}

// ---------------- fused agg after layer1 + MLP head ----------------
__global__ void __launch_bounds__(256)
agg_head_kernel(const __half* __restrict__ hs,
                const int* __restrict__ rowptr, const int* __restrict__ adj,
                const float* __restrict__ cb,
                const float* __restrict__ W0, const float* __restrict__ b0,
                const float* __restrict__ W1, const float* __restrict__ b1,
                float* __restrict__ out, int N) {
    __shared__ float w0t[10 * 104];  // w0t[j*104+k] = W0[k*10+j]; k>=100 -> 0
    __shared__ float b0s[10];
    __shared__ float w1s[10];
    __shared__ float b1v;
    int tid = threadIdx.x;

    for (int i = tid; i < 1040; i += 256) {
        int j = i / 104, k = i - j * 104;
        w0t[i] = (k < 100) ? __ldg(W0 + k * 10 + j) : 0.f;
    }
    if (tid < 10) { b0s[tid] = __ldg(b0 + tid); w1s[tid] = __ldg(W1 + tid); }
    if (tid == 0) b1v = __ldg(b1);
    __syncthreads();

    int node = (blockIdx.x * 256 + tid) >> 5;
    int lane = tid & 31;
    if (node >= N) return;
    bool act = lane < 13;

    float s[8];
#pragma unroll
    for (int i = 0; i < 8; i++) s[i] = 0.f;
    if (act) acc8(s, __ldg((const float4*)(hs + (size_t)node * 128) + lane));

    int beg = rowptr[node];
    int end = rowptr[node + 1];
    for (int base = beg; base < end; base += 32) {
        int idx = base + lane;
        int my = (idx < end) ? __ldg(adj + idx) : 0;
        int cnt = min(32, end - base);
#pragma unroll 8
        for (int j = 0; j < cnt; j++) {
            int sj = __shfl_sync(0xffffffffu, my, j);
            if (act) acc8(s, __ldg((const float4*)(hs + (size_t)sj * 128) + lane));
        }
    }

    // x2 = dinv*sum + cb1 (lane owns cols 8*lane..8*lane+7; lane12 upper 4 = 0 via w0t pads)
    float x2[8];
#pragma unroll
    for (int i = 0; i < 8; i++) x2[i] = 0.f;
    if (act) {
        float di = g_dinv[node];
        float4 blo = __ldg((const float4*)cb + 2 * lane);
        x2[0] = di * s[0] + blo.x; x2[1] = di * s[1] + blo.y;
        x2[2] = di * s[2] + blo.z; x2[3] = di * s[3] + blo.w;
        if (lane < 12) {
            float4 bhi = __ldg((const float4*)cb + 2 * lane + 1);
            x2[4] = di * s[4] + bhi.x; x2[5] = di * s[5] + bhi.y;
            x2[6] = di * s[6] + bhi.z; x2[7] = di * s[7] + bhi.w;
        }
    }

    float p[10];
#pragma unroll
    for (int j = 0; j < 10; j++) {
        float4 wl = make_float4(0.f, 0.f, 0.f, 0.f);
        float4 wh = make_float4(0.f, 0.f, 0.f, 0.f);
        if (act) {
            wl = *(const float4*)(w0t + j * 104 + 8 * lane);
            wh = *(const float4*)(w0t + j * 104 + 8 * lane + 4);
        }
        p[j] = x2[0] * wl.x + x2[1] * wl.y + x2[2] * wl.z + x2[3] * wl.w
             + x2[4] * wh.x + x2[5] * wh.y + x2[6] * wh.z + x2[7] * wh.w;
    }
#pragma unroll
    for (int j = 0; j < 10; j++) {
#pragma unroll
        for (int off = 16; off > 0; off >>= 1)
            p[j] += __shfl_xor_sync(0xffffffffu, p[j], off);
    }
    if (lane == 0) {
        float o = b1v;
#pragma unroll
        for (int j = 0; j < 10; j++) o += fmaxf(p[j] + b0s[j], 0.f) * w1s[j];
        out[node] = o;
    }
}

extern "C" void kernel_launch(void* const* d_in, const int* in_sizes, int n_in,
                              void* d_out, int out_size) {
    const float* x   = (const float*)d_in[0];
    const int*   ei  = (const int*)d_in[1];
    const float* W0  = (const float*)d_in[2];
    const float* cb0 = (const float*)d_in[3];
    const float* W1  = (const float*)d_in[4];
    const float* cb1 = (const float*)d_in[5];
    const float* lW0 = (const float*)d_in[6];
    const float* lb0 = (const float*)d_in[7];
    const float* lW1 = (const float*)d_in[8];
    const float* lb1 = (const float*)d_in[9];
    float* out = (float*)d_out;

    int N = in_sizes[0] / 100;
    int E = in_sizes[1] / 2;
    const int* src = ei;
    const int* dst = ei + E;

    size_t gemm_smem = (128 + 104) * SX_STRIDE * sizeof(__half);  // 55.7 KB -> 3 blocks/SM
    cudaFuncSetAttribute(gemm_mma_kernel,
                         cudaFuncAttributeMaxDynamicSharedMemorySize, (int)gemm_smem);

    __half* hs;
    float* acc;
    int *rowptr, *adj;
    cudaGetSymbolAddress((void**)&hs, g_hs);
    cudaGetSymbolAddress((void**)&acc, g_acc);
    cudaGetSymbolAddress((void**)&rowptr, g_rowptr);
    cudaGetSymbolAddress((void**)&adj, g_adj);

    cudaStream_t s2;
    cudaStreamCreateWithFlags(&s2, cudaStreamNonBlocking);
    cudaEvent_t ev0, evH, evD, ev1;
    cudaEventCreateWithFlags(&ev0, cudaEventDisableTiming);
    cudaEventCreateWithFlags(&evH, cudaEventDisableTiming);
    cudaEventCreateWithFlags(&evD, cudaEventDisableTiming);
    cudaEventCreateWithFlags(&ev1, cudaEventDisableTiming);

    cudaEventRecord(ev0, 0);
    cudaStreamWaitEvent(s2, ev0, 0);

    // overlap: sumsq (s2) || hist (default)
    long n_elem = (long)N * 100;
    sumsq_kernel<<<512, 256, 0, s2>>>(x, n_elem);
    hist_kernel<<<(E + 255) / 256, 256>>>(dst, E);
    cudaEventRecord(evH, 0);
    cudaStreamWaitEvent(s2, evH, 0);

    // s2: scan1 (local scan + dinv + norm2) -> scan23 -> fill
    int nscan = (N + 256) / 256;
    scan1_kernel<<<nscan, 256, 0, s2>>>(N);
    cudaEventRecord(evD, s2);
    scan23_kernel<<<nscan, 256, 0, s2>>>(nscan, N, E);
    fill_kernel<<<(E + 255) / 256, 256, 0, s2>>>(src, dst, E);
    cudaEventRecord(ev1, s2);

    // default: gemm0 (needs dinv) overlaps scan23 + fill
    cudaStreamWaitEvent(0, evD, 0);
    int gblocks = (N + 127) / 128;
    gemm_mma_kernel<<<gblocks, 256, gemm_smem>>>(x, W0, hs, N);

    cudaStreamWaitEvent(0, ev1, 0);  // join

    int ablocks = (N + 7) / 8;
    agg_kernel<<<ablocks, 256>>>(hs, acc, rowptr, adj, cb0, N);
    gemm_mma_kernel<<<gblocks, 256, gemm_smem>>>(acc, W1, hs, N);
    agg_head_kernel<<<ablocks, 256>>>(hs, rowptr, adj, cb1, lW0, lb0, lW1, lb1, out, N);
}

// round 14
// speedup vs baseline: 1.2485x; 1.2485x over previous
#include <cuda_runtime.h>
#include <cuda_fp16.h>
#include <math.h>
#include <stdint.h>

// ---------------- scratch (no allocation allowed) ----------------
__device__ __half g_hs[6400000];   // 50000 x 128 halves (256B-aligned rows)
__device__ float  g_acc[5000000];  // 50000 x 100 fp32 (layer-1 input)
__device__ float  g_dinv[50048];
__device__ int    g_cnt[50048];    // statically zero; re-zeroed by scan23 each call
__device__ int    g_rowptr[50049];
__device__ int    g_off[50049];
__device__ int    g_adj[800064];
__device__ int    g_bsum[256];
__device__ float  g_partials[512];
__device__ float  g_norm2;

// ---------------- ||x||^2 partial sums (s2, overlaps hist) ----------------
__global__ void sumsq_kernel(const float* __restrict__ x, long n) {
    int gs = gridDim.x * blockDim.x;
    float s = 0.f;
    for (long i = (long)blockIdx.x * blockDim.x + threadIdx.x; i < n; i += gs) {
        float v = x[i];
        s += v * v;
    }
    __shared__ float sm[256];
    sm[threadIdx.x] = s;
    __syncthreads();
    for (int o = 128; o > 0; o >>= 1) {
        if (threadIdx.x < o) sm[threadIdx.x] += sm[threadIdx.x + o];
        __syncthreads();
    }
    if (threadIdx.x == 0) g_partials[blockIdx.x] = sm[0];
}

__global__ void hist_kernel(const int* __restrict__ dst, int E) {
    int i = blockIdx.x * blockDim.x + threadIdx.x;
    if (i < E) atomicAdd(&g_cnt[dst[i]], 1);
}

// ---------------- scan1: block-local scan + dinv + norm2 finalize ----------------
__global__ void scan1_kernel(int N) {
    __shared__ int sm[256];
    int node = blockIdx.x * 256 + threadIdx.x;
    int c = (node < N) ? g_cnt[node] : 0;
    if (node < N) g_dinv[node] = rsqrtf((float)(c + 1));  // +1 self-loop
    if (blockIdx.x == 0) {
        __shared__ float fm[256];
        fm[threadIdx.x] = g_partials[threadIdx.x] + g_partials[threadIdx.x + 256];
        __syncthreads();
        for (int o = 128; o > 0; o >>= 1) {
            if (threadIdx.x < o) fm[threadIdx.x] += fm[threadIdx.x + o];
            __syncthreads();
        }
        if (threadIdx.x == 0) g_norm2 = fm[0];
    }
    sm[threadIdx.x] = c;
    __syncthreads();
    for (int o = 1; o < 256; o <<= 1) {
        int v = (threadIdx.x >= o) ? sm[threadIdx.x - o] : 0;
        __syncthreads();
        sm[threadIdx.x] += v;
        __syncthreads();
    }
    if (node <= N) g_rowptr[node] = sm[threadIdx.x] - c;
    if (threadIdx.x == 255) g_bsum[blockIdx.x] = sm[255];
}

// ---------------- scan23: per-block re-scan of bsums + finalize rowptr/off/cnt ----------------
__global__ void scan23_kernel(int nb, int N, int E) {
    __shared__ int sm[256];
    int c = (threadIdx.x < nb) ? g_bsum[threadIdx.x] : 0;
    sm[threadIdx.x] = c;
    __syncthreads();
    for (int o = 1; o < 256; o <<= 1) {
        int v = (threadIdx.x >= o) ? sm[threadIdx.x - o] : 0;
        __syncthreads();
        sm[threadIdx.x] += v;
        __syncthreads();
    }
    __syncthreads();
    int boff = (blockIdx.x > 0) ? sm[blockIdx.x - 1] : 0;  // exclusive block offset
    int node = blockIdx.x * 256 + threadIdx.x;
    if (node < N) {
        int r = g_rowptr[node] + boff;
        g_rowptr[node] = r;
        g_off[node] = r;
        g_cnt[node] = 0;  // reset for next graph replay
    } else if (node == N) {
        g_rowptr[N] = E;
    }
}

__global__ void fill_kernel(const int* __restrict__ src, const int* __restrict__ dst, int E) {
    int i = blockIdx.x * blockDim.x + threadIdx.x;
    if (i < E) {
        int pos = atomicAdd(&g_off[dst[i]], 1);
        g_adj[pos] = src[i];
    }
}

// ---------------- fp16 tensor-core GEMM: hs = fp16(dinv[row] * (X @ W)) ----------------
#define SX_STRIDE 120
__global__ void __launch_bounds__(256, 3)
gemm_mma_kernel(const float* __restrict__ X, const float* __restrict__ W,
                __half* __restrict__ hs, int N) {
    extern __shared__ __half smem_h[];
    __half* sX = smem_h;                    // 128 x 120
    __half* sWt = smem_h + 128 * SX_STRIDE; // 104 x 120 (n-major, k contiguous)
    int tid = threadIdx.x;
    int row0 = blockIdx.x * 128;
    const uint2 z2 = make_uint2(0u, 0u);

    for (int i = tid; i < 104 * SX_STRIDE / 4; i += 256)
        ((uint2*)sWt)[i] = z2;

    {
        int r = tid >> 1, h = tid & 1;
        int gr = row0 + r;
        __half* drow = sX + r * SX_STRIDE;
        if (gr < N) {
            const float4* srcp = (const float4*)(X + (size_t)gr * 100);
#pragma unroll
            for (int t = 0; t < 13; t++) {
                int c4 = h * 13 + t;
                if (c4 < 25) {
                    float4 v = __ldg(srcp + c4);
                    __half2 lo = __floats2half2_rn(v.x, v.y);
                    __half2 hi = __floats2half2_rn(v.z, v.w);
                    uint2 u;
                    u.x = *(uint32_t*)&lo; u.y = *(uint32_t*)&hi;
                    *(uint2*)(drow + c4 * 4) = u;
                }
            }
        } else {
#pragma unroll
            for (int t = 0; t < 13; t++) {
                int c4 = h * 13 + t;
                if (c4 < 25) *(uint2*)(drow + c4 * 4) = z2;
            }
        }
        if (h) {
            *(uint2*)(drow + 100) = z2;
            *(uint2*)(drow + 104) = z2;
            *(uint2*)(drow + 108) = z2;
        }
    }
    __syncthreads();

    for (int i = tid; i < 10000; i += 256) {
        int k = i / 100, n = i - k * 100;
        sWt[n * SX_STRIDE + k] = __float2half_rn(__ldg(W + i));
    }
    __syncthreads();

    int warp = tid >> 5, lane = tid & 31;
    int grp = lane >> 2, tig = lane & 3;
    const __half* xw0 = sX + (warp * 16 + grp) * SX_STRIDE;
    const __half* xw1 = xw0 + 8 * SX_STRIDE;

    float acc[13][4];
#pragma unroll
    for (int nt = 0; nt < 13; nt++)
#pragma unroll
        for (int i = 0; i < 4; i++) acc[nt][i] = 0.f;

#pragma unroll
    for (int kc = 0; kc < 7; kc++) {
        int k0 = kc * 16;
        uint32_t a0 = *(const uint32_t*)(xw0 + k0 + 2 * tig);
        uint32_t a1 = *(const uint32_t*)(xw1 + k0 + 2 * tig);
        uint32_t a2 = *(const uint32_t*)(xw0 + k0 + 2 * tig + 8);
        uint32_t a3 = *(const uint32_t*)(xw1 + k0 + 2 * tig + 8);
        const __half* wb = sWt + grp * SX_STRIDE + k0 + 2 * tig;
#pragma unroll
        for (int nt = 0; nt < 13; nt++) {
            uint32_t b0 = *(const uint32_t*)(wb + nt * 8 * SX_STRIDE);
            uint32_t b1 = *(const uint32_t*)(wb + nt * 8 * SX_STRIDE + 8);
            asm volatile(
                "mma.sync.aligned.m16n8k16.row.col.f32.f16.f16.f32 "
                "{%0,%1,%2,%3}, {%4,%5,%6,%7}, {%8,%9}, {%0,%1,%2,%3};"
                : "+f"(acc[nt][0]), "+f"(acc[nt][1]), "+f"(acc[nt][2]), "+f"(acc[nt][3])
                : "r"(a0), "r"(a1), "r"(a2), "r"(a3), "r"(b0), "r"(b1));
        }
    }

    int gr0 = row0 + warp * 16 + grp;
    int gr1 = gr0 + 8;
    float s0 = (gr0 < N) ? g_dinv[gr0] : 0.f;
    float s1 = (gr1 < N) ? g_dinv[gr1] : 0.f;
#pragma unroll
    for (int nt = 0; nt < 13; nt++) {
        int col = nt * 8 + 2 * tig;
        if (gr0 < N) {
            __half2 h = __floats2half2_rn(acc[nt][0] * s0, acc[nt][1] * s0);
            *(__half2*)(hs + (size_t)gr0 * 128 + col) = h;
        }
        if (gr1 < N) {
            __half2 h = __floats2half2_rn(acc[nt][2] * s1, acc[nt][3] * s1);
            *(__half2*)(hs + (size_t)gr1 * 128 + col) = h;
        }
    }
}

// ---------------- agg after layer0: acc = (dinv_i*rsqrt(norm2))*sum + cb0 (fp32) ----------------
// [R12-proven loop: 25 active lanes x uint2]
__global__ void __launch_bounds__(256)
agg_kernel(const __half* __restrict__ hs, float* __restrict__ acc,
           const int* __restrict__ rowptr, const int* __restrict__ adj,
           const float* __restrict__ cb, int N) {
    int node = (blockIdx.x * 256 + threadIdx.x) >> 5;
    int lane = threadIdx.x & 31;
    if (node >= N) return;
    bool act = lane < 25;

    float4 sum = make_float4(0.f, 0.f, 0.f, 0.f);
    if (act) {
        uint2 raw = __ldg((const uint2*)(hs + (size_t)node * 128) + lane);
        float2 f0 = __half22float2(*(const __half2*)&raw.x);
        float2 f1 = __half22float2(*(const __half2*)&raw.y);
        sum.x = f0.x; sum.y = f0.y; sum.z = f1.x; sum.w = f1.y;
    }

    int beg = rowptr[node];
    int end = rowptr[node + 1];
    for (int base = beg; base < end; base += 32) {
        int idx = base + lane;
        int my = (idx < end) ? __ldg(adj + idx) : 0;
        int cnt = min(32, end - base);
#pragma unroll 8
        for (int j = 0; j < cnt; j++) {
            int s = __shfl_sync(0xffffffffu, my, j);
            if (act) {
                uint2 raw = __ldg((const uint2*)(hs + (size_t)s * 128) + lane);
                float2 f0 = __half22float2(*(const __half2*)&raw.x);
                float2 f1 = __half22float2(*(const __half2*)&raw.y);
                sum.x += f0.x; sum.y += f0.y; sum.z += f1.x; sum.w += f1.y;
            }
        }
    }
    if (act) {
        float os = g_dinv[node] * rsqrtf(g_norm2);
        float4 b = __ldg((const float4*)cb + lane);
        sum.x = sum.x * os + b.x; sum.y = sum.y * os + b.y;
        sum.z = sum.z * os + b.z; sum.w = sum.w * os + b.w;
        *((float4*)(acc + (size_t)node * 100) + lane) = sum;
    }
}

// ---------------- fused agg after layer1 + MLP head  [R12-proven] ----------------
__global__ void __launch_bounds__(256)
agg_head_kernel(const __half* __restrict__ hs,
                const int* __restrict__ rowptr, const int* __restrict__ adj,
                const float* __restrict__ cb,
                const float* __restrict__ W0, const float* __restrict__ b0,
                const float* __restrict__ W1, const float* __restrict__ b1,
                float* __restrict__ out, int N) {
    __shared__ float w0t[10 * 104];  // w0t[j*104+k] = W0[k*10+j]
    __shared__ float b0s[10];
    __shared__ float w1s[10];
    __shared__ float b1v;
    int tid = threadIdx.x;

    for (int i = tid; i < 1000; i += 256) {
        int k = i / 10, j = i - k * 10;
        w0t[j * 104 + k] = __ldg(W0 + i);
    }
    if (tid < 10) { b0s[tid] = __ldg(b0 + tid); w1s[tid] = __ldg(W1 + tid); }
    if (tid == 0) b1v = __ldg(b1);
    __syncthreads();

    int node = (blockIdx.x * 256 + tid) >> 5;
    int lane = tid & 31;
    if (node >= N) return;
    bool act = lane < 25;

    float4 sum = make_float4(0.f, 0.f, 0.f, 0.f);
    if (act) {
        uint2 raw = __ldg((const uint2*)(hs + (size_t)node * 128) + lane);
        float2 f0 = __half22float2(*(const __half2*)&raw.x);
        float2 f1 = __half22float2(*(const __half2*)&raw.y);
        sum.x = f0.x; sum.y = f0.y; sum.z = f1.x; sum.w = f1.y;
    }
    int beg = rowptr[node];
    int end = rowptr[node + 1];
    for (int base = beg; base < end; base += 32) {
        int idx = base + lane;
        int my = (idx < end) ? __ldg(adj + idx) : 0;
        int cnt = min(32, end - base);
#pragma unroll 8
        for (int j = 0; j < cnt; j++) {
            int s = __shfl_sync(0xffffffffu, my, j);
            if (act) {
                uint2 raw = __ldg((const uint2*)(hs + (size_t)s * 128) + lane);
                float2 f0 = __half22float2(*(const __half2*)&raw.x);
                float2 f1 = __half22float2(*(const __half2*)&raw.y);
                sum.x += f0.x; sum.y += f0.y; sum.z += f1.x; sum.w += f1.y;
            }
        }
    }

    float4 x2 = make_float4(0.f, 0.f, 0.f, 0.f);
    if (act) {
        float di = g_dinv[node];
        float4 b = __ldg((const float4*)cb + lane);
        x2.x = di * sum.x + b.x; x2.y = di * sum.y + b.y;
        x2.z = di * sum.z + b.z; x2.w = di * sum.w + b.w;
    }

    float p[10];
#pragma unroll
    for (int j = 0; j < 10; j++) {
        float4 w = make_float4(0.f, 0.f, 0.f, 0.f);
        if (act) w = *(const float4*)(w0t + j * 104 + 4 * lane);
        p[j] = x2.x * w.x + x2.y * w.y + x2.z * w.z + x2.w * w.w;
    }
#pragma unroll
    for (int j = 0; j < 10; j++) {
#pragma unroll
        for (int off = 16; off > 0; off >>= 1)
            p[j] += __shfl_xor_sync(0xffffffffu, p[j], off);
    }
    if (lane == 0) {
        float o = b1v;
#pragma unroll
        for (int j = 0; j < 10; j++) o += fmaxf(p[j] + b0s[j], 0.f) * w1s[j];
        out[node] = o;
    }
}

extern "C" void kernel_launch(void* const* d_in, const int* in_sizes, int n_in,
                              void* d_out, int out_size) {
    const float* x   = (const float*)d_in[0];
    const int*   ei  = (const int*)d_in[1];
    const float* W0  = (const float*)d_in[2];
    const float* cb0 = (const float*)d_in[3];
    const float* W1  = (const float*)d_in[4];
    const float* cb1 = (const float*)d_in[5];
    const float* lW0 = (const float*)d_in[6];
    const float* lb0 = (const float*)d_in[7];
    const float* lW1 = (const float*)d_in[8];
    const float* lb1 = (const float*)d_in[9];
    float* out = (float*)d_out;

    int N = in_sizes[0] / 100;
    int E = in_sizes[1] / 2;
    const int* src = ei;
    const int* dst = ei + E;

    size_t gemm_smem = (128 + 104) * SX_STRIDE * sizeof(__half);  // 55.7 KB -> 3 blocks/SM
    cudaFuncSetAttribute(gemm_mma_kernel,
                         cudaFuncAttributeMaxDynamicSharedMemorySize, (int)gemm_smem);

    __half* hs;
    float* acc;
    int *rowptr, *adj;
    cudaGetSymbolAddress((void**)&hs, g_hs);
    cudaGetSymbolAddress((void**)&acc, g_acc);
    cudaGetSymbolAddress((void**)&rowptr, g_rowptr);
    cudaGetSymbolAddress((void**)&adj, g_adj);

    cudaStream_t s2;
    cudaStreamCreateWithFlags(&s2, cudaStreamNonBlocking);
    cudaEvent_t ev0, evH, evD, ev1;
    cudaEventCreateWithFlags(&ev0, cudaEventDisableTiming);
    cudaEventCreateWithFlags(&evH, cudaEventDisableTiming);
    cudaEventCreateWithFlags(&evD, cudaEventDisableTiming);
    cudaEventCreateWithFlags(&ev1, cudaEventDisableTiming);

    cudaEventRecord(ev0, 0);
    cudaStreamWaitEvent(s2, ev0, 0);

    // overlap: sumsq (s2) || hist (default)
    long n_elem = (long)N * 100;
    sumsq_kernel<<<512, 256, 0, s2>>>(x, n_elem);
    hist_kernel<<<(E + 255) / 256, 256>>>(dst, E);
    cudaEventRecord(evH, 0);
    cudaStreamWaitEvent(s2, evH, 0);

    // s2: scan1 (local scan + dinv + norm2) -> scan23 -> fill
    int nscan = (N + 256) / 256;
    scan1_kernel<<<nscan, 256, 0, s2>>>(N);
    cudaEventRecord(evD, s2);
    scan23_kernel<<<nscan, 256, 0, s2>>>(nscan, N, E);
    fill_kernel<<<(E + 255) / 256, 256, 0, s2>>>(src, dst, E);
    cudaEventRecord(ev1, s2);

    // default: gemm0 (needs dinv) overlaps scan23 + fill
    cudaStreamWaitEvent(0, evD, 0);
    int gblocks = (N + 127) / 128;
    gemm_mma_kernel<<<gblocks, 256, gemm_smem>>>(x, W0, hs, N);

    cudaStreamWaitEvent(0, ev1, 0);  // join

    int ablocks = (N + 7) / 8;
    agg_kernel<<<ablocks, 256>>>(hs, acc, rowptr, adj, cb0, N);
    gemm_mma_kernel<<<gblocks, 256, gemm_smem>>>(acc, W1, hs, N);
    agg_head_kernel<<<ablocks, 256>>>(hs, rowptr, adj, cb1, lW0, lb0, lW1, lb1, out, N);
}